// round 8
// baseline (speedup 1.0000x reference)
#include <cuda_runtime.h>
#include <math.h>

#define BATCH 8
#define SEQ   2048
#define DIM   1024
#define MSZ   (BATCH*SEQ)
typedef unsigned int u32;

#define NXD ((size_t)MSZ*DIM)
#define NPP ((size_t)BATCH*SEQ*SEQ)

// interleaved {hi,lo} tf32-exact planes
__device__ float2 g_q2 [NXD];
__device__ float2 g_k2 [NXD];
__device__ float2 g_vt2[NXD];   // v^T: [b][e][s]
__device__ float2 g_p2 [NPP];

// ---------------- helpers ----------------
__device__ __forceinline__ void cvt2(float x, u32& h, u32& l) {
    asm("cvt.rna.tf32.f32 %0, %1;" : "=r"(h) : "f"(x));
    float r = x - __uint_as_float(h);
    asm("cvt.rna.tf32.f32 %0, %1;" : "=r"(l) : "f"(r));
}
__device__ __forceinline__ void cvt2f(float x, float& h, float& l) {
    u32 uh, ul; cvt2(x, uh, ul);
    h = __uint_as_float(uh); l = __uint_as_float(ul);
}
__device__ __forceinline__ void mma8(float* c, const u32* a, const u32* b) {
    asm volatile(
        "mma.sync.aligned.m16n8k8.row.col.f32.tf32.tf32.f32 "
        "{%0,%1,%2,%3}, {%4,%5,%6,%7}, {%8,%9}, {%0,%1,%2,%3};"
        : "+f"(c[0]), "+f"(c[1]), "+f"(c[2]), "+f"(c[3])
        : "r"(a[0]), "r"(a[1]), "r"(a[2]), "r"(a[3]), "r"(b[0]), "r"(b[1]));
}
__device__ __forceinline__ void mma8f(float* c, float a0, float a1, float a2, float a3,
                                      float b0, float b1) {
    asm volatile(
        "mma.sync.aligned.m16n8k8.row.col.f32.tf32.tf32.f32 "
        "{%0,%1,%2,%3}, {%4,%5,%6,%7}, {%8,%9}, {%0,%1,%2,%3};"
        : "+f"(c[0]), "+f"(c[1]), "+f"(c[2]), "+f"(c[3])
        : "r"(__float_as_uint(a0)), "r"(__float_as_uint(a1)),
          "r"(__float_as_uint(a2)), "r"(__float_as_uint(a3)),
          "r"(__float_as_uint(b0)), "r"(__float_as_uint(b1)));
}
__device__ __forceinline__ u32 smem_u32(const void* p) {
    u32 a;
    asm("{ .reg .u64 t; cvta.to.shared.u64 t, %1; cvt.u32.u64 %0, t; }" : "=r"(a) : "l"(p));
    return a;
}
__device__ __forceinline__ void cp16(u32 s, const void* g) {
    asm volatile("cp.async.cg.shared.global [%0], [%1], 16;" :: "r"(s), "l"(g));
}
#define CP_COMMIT() asm volatile("cp.async.commit_group;" ::: "memory")
#define CP_WAIT0()  asm volatile("cp.async.wait_group 0;" ::: "memory")

// ---------------------------------------------------------------------------
// Projection GEMM (round-7 proven core). Raw fp32 in, in-register tf32 split,
// epilogue writes interleaved {hi,lo} float2 planes.
// ---------------------------------------------------------------------------
#define LDT 36
#define TILE_F (128*LDT)
#define SMEM_PROJ (4*TILE_F*4)   // 73728 B

__global__ __launch_bounds__(256, 2) void gemm_proj(
    const float* __restrict__ A, const float* __restrict__ B,
    const float* __restrict__ bias, int biasRow,
    float2* __restrict__ C2, int K, size_t sA, size_t sB, size_t sC, int ldc)
{
    extern __shared__ float sm[];
    const u32 sbase = smem_u32(sm);
    const int tid = threadIdx.x;
    const int wid = tid >> 5, lane = tid & 31;
    const int g = lane >> 2, tig = lane & 3;
    const int wm = (wid >> 2) * 64, wn = (wid & 3) * 32;
    const int z = blockIdx.z;

    const float* Ab = A + z * sA + (size_t)(blockIdx.y * 128) * K;
    const float* Bb = B + z * sB + (size_t)(blockIdx.x * 128) * K;

    const int lr = tid >> 3;
    const int lc4 = (tid & 7) * 4;

    float acc[4][4][4];
#pragma unroll
    for (int mi = 0; mi < 4; mi++)
#pragma unroll
        for (int ni = 0; ni < 4; ni++)
#pragma unroll
            for (int r = 0; r < 4; r++) acc[mi][ni][r] = 0.0f;

    const int nch = K / 32;

    auto issue = [&](int c, int buf) {
        const int k0 = c * 32;
        const u32 sA0 = sbase + (u32)(buf * 2 * TILE_F) * 4;
        const u32 sB0 = sA0 + (u32)TILE_F * 4;
#pragma unroll
        for (int i = 0; i < 4; i++) {
            const int row = lr + i * 32;
            cp16(sA0 + (u32)(row * LDT + lc4) * 4, Ab + (size_t)row * K + k0 + lc4);
            cp16(sB0 + (u32)(row * LDT + lc4) * 4, Bb + (size_t)row * K + k0 + lc4);
        }
        CP_COMMIT();
    };

    issue(0, 0);

    for (int c = 0; c < nch; c++) {
        const int p = c & 1;
        CP_WAIT0();
        __syncthreads();
        if (c + 1 < nch) issue(c + 1, p ^ 1);

        const float* As = sm + p * 2 * TILE_F;
        const float* Bs = As + TILE_F;
#pragma unroll
        for (int ks = 0; ks < 4; ks++) {
            const int kc = ks * 8 + tig;
            u32 ah[4][4], al[4][4], bh[4][2], bl[4][2];
#pragma unroll
            for (int mi = 0; mi < 4; mi++) {
                const int r0 = (wm + mi * 16 + g) * LDT;
                cvt2(As[r0 + kc],               ah[mi][0], al[mi][0]);
                cvt2(As[r0 + 8 * LDT + kc],     ah[mi][1], al[mi][1]);
                cvt2(As[r0 + kc + 4],           ah[mi][2], al[mi][2]);
                cvt2(As[r0 + 8 * LDT + kc + 4], ah[mi][3], al[mi][3]);
            }
#pragma unroll
            for (int ni = 0; ni < 4; ni++) {
                const int rn = (wn + ni * 8 + g) * LDT;
                cvt2(Bs[rn + kc],     bh[ni][0], bl[ni][0]);
                cvt2(Bs[rn + kc + 4], bh[ni][1], bl[ni][1]);
            }
#pragma unroll
            for (int mi = 0; mi < 4; mi++)
#pragma unroll
                for (int ni = 0; ni < 4; ni++) mma8(acc[mi][ni], ah[mi], bh[ni]);
#pragma unroll
            for (int mi = 0; mi < 4; mi++)
#pragma unroll
                for (int ni = 0; ni < 4; ni++) mma8(acc[mi][ni], ah[mi], bl[ni]);
#pragma unroll
            for (int mi = 0; mi < 4; mi++)
#pragma unroll
                for (int ni = 0; ni < 4; ni++) mma8(acc[mi][ni], al[mi], bh[ni]);
        }
        __syncthreads();
    }

    // epilogue: bias, split -> interleaved planes
    float2* Cz = C2 + z * sC;
#pragma unroll
    for (int mi = 0; mi < 4; mi++) {
        const int row0 = blockIdx.y * 128 + wm + mi * 16 + g;
        const float br0 = (bias && biasRow) ? bias[row0] : 0.0f;
        const float br1 = (bias && biasRow) ? bias[row0 + 8] : 0.0f;
#pragma unroll
        for (int ni = 0; ni < 4; ni++) {
            const int col0 = blockIdx.x * 128 + wn + ni * 8 + tig * 2;
            float v[4];
            v[0] = acc[mi][ni][0]; v[1] = acc[mi][ni][1];
            v[2] = acc[mi][ni][2]; v[3] = acc[mi][ni][3];
            if (bias) {
                if (biasRow) { v[0] += br0; v[1] += br0; v[2] += br1; v[3] += br1; }
                else {
                    const float b0 = bias[col0], b1 = bias[col0 + 1];
                    v[0] += b0; v[1] += b1; v[2] += b0; v[3] += b1;
                }
            }
            const size_t o0 = (size_t)row0 * ldc + col0;
            const size_t o1 = (size_t)(row0 + 8) * ldc + col0;
            float2 e;
            cvt2f(v[0], e.x, e.y); Cz[o0] = e;
            cvt2f(v[1], e.x, e.y); Cz[o0 + 1] = e;
            cvt2f(v[2], e.x, e.y); Cz[o1] = e;
            cvt2f(v[3], e.x, e.y); Cz[o1 + 1] = e;
        }
    }
}

// ---------------------------------------------------------------------------
// Big GEMM (QK^T, P*V): operands interleaved {hi,lo} float2.
// C[m,n] = scale * sum_k A[m,k]*B[n,k], fp32 out.
// 128x128 tile, KC=16 float2, 256 thr (8 warps 2m x 4n), 2 CTAs/SM.
// Inner loop: LDS.64 + HMMA only. nprod: 3 = hh+hl+lh, 2 = hh+lh.
// ---------------------------------------------------------------------------
#define LD2 20                       // float2 row stride: 40 floats == 8 banks
#define T2 (128*LD2)                 // 2560 float2 per tile
#define SMEM_BIG (2*2*T2*8)          // 81920 B

__global__ __launch_bounds__(256, 2) void gemm_big2(
    const float2* __restrict__ A, const float2* __restrict__ B,
    float* __restrict__ C, int K, float scale,
    size_t sA, size_t sB, size_t sC, int ldc, int nprod)
{
    extern __shared__ float2 sm2[];
    const u32 sbase = smem_u32(sm2);
    const int tid = threadIdx.x;
    const int wid = tid >> 5, lane = tid & 31;
    const int g = lane >> 2, tig = lane & 3;
    const int wm = (wid >> 2) * 64, wn = (wid & 3) * 32;
    const int z = blockIdx.z;

    const float2* Ab = A + z * sA + (size_t)(blockIdx.y * 128) * K;
    const float2* Bb = B + z * sB + (size_t)(blockIdx.x * 128) * K;

    const int lrow = tid >> 3;           // 0..31 (+32/64/96)
    const int lc2 = (tid & 7) * 2;       // float2 col 0..14

    float acc[4][4][4];
#pragma unroll
    for (int mi = 0; mi < 4; mi++)
#pragma unroll
        for (int ni = 0; ni < 4; ni++)
#pragma unroll
            for (int r = 0; r < 4; r++) acc[mi][ni][r] = 0.0f;

    const int nch = K / 16;

    auto issue = [&](int c, int buf) {
        const int k0 = c * 16;
        const u32 sA0 = sbase + (u32)(buf * 2 * T2) * 8;
        const u32 sB0 = sA0 + (u32)T2 * 8;
#pragma unroll
        for (int i = 0; i < 4; i++) {
            const int row = lrow + i * 32;
            cp16(sA0 + (u32)(row * LD2 + lc2) * 8, Ab + (size_t)row * K + k0 + lc2);
            cp16(sB0 + (u32)(row * LD2 + lc2) * 8, Bb + (size_t)row * K + k0 + lc2);
        }
        CP_COMMIT();
    };

    issue(0, 0);

    for (int c = 0; c < nch; c++) {
        const int p = c & 1;
        CP_WAIT0();
        __syncthreads();
        if (c + 1 < nch) issue(c + 1, p ^ 1);

        const float2* As = sm2 + p * 2 * T2;
        const float2* Bs = As + T2;

#pragma unroll
        for (int ks = 0; ks < 2; ks++) {
            const int kc = ks * 8 + tig;
            float2 a2[4][4], b2[4][2];
#pragma unroll
            for (int mi = 0; mi < 4; mi++) {
                const int r0 = (wm + mi * 16 + g) * LD2;
                a2[mi][0] = As[r0 + kc];
                a2[mi][1] = As[r0 + 8 * LD2 + kc];
                a2[mi][2] = As[r0 + kc + 4];
                a2[mi][3] = As[r0 + 8 * LD2 + kc + 4];
            }
#pragma unroll
            for (int ni = 0; ni < 4; ni++) {
                const int rn = (wn + ni * 8 + g) * LD2;
                b2[ni][0] = Bs[rn + kc];
                b2[ni][1] = Bs[rn + kc + 4];
            }
            // hh
#pragma unroll
            for (int mi = 0; mi < 4; mi++)
#pragma unroll
                for (int ni = 0; ni < 4; ni++)
                    mma8f(acc[mi][ni], a2[mi][0].x, a2[mi][1].x, a2[mi][2].x, a2[mi][3].x,
                          b2[ni][0].x, b2[ni][1].x);
            // lh
#pragma unroll
            for (int mi = 0; mi < 4; mi++)
#pragma unroll
                for (int ni = 0; ni < 4; ni++)
                    mma8f(acc[mi][ni], a2[mi][0].y, a2[mi][1].y, a2[mi][2].y, a2[mi][3].y,
                          b2[ni][0].x, b2[ni][1].x);
            // hl (QK only)
            if (nprod == 3) {
#pragma unroll
                for (int mi = 0; mi < 4; mi++)
#pragma unroll
                    for (int ni = 0; ni < 4; ni++)
                        mma8f(acc[mi][ni], a2[mi][0].x, a2[mi][1].x, a2[mi][2].x, a2[mi][3].x,
                              b2[ni][0].y, b2[ni][1].y);
            }
        }
        __syncthreads();
    }

    // epilogue: fp32 out
    float* Cz = C + z * sC;
#pragma unroll
    for (int mi = 0; mi < 4; mi++) {
        const int row0 = blockIdx.y * 128 + wm + mi * 16 + g;
#pragma unroll
        for (int ni = 0; ni < 4; ni++) {
            const int col0 = blockIdx.x * 128 + wn + ni * 8 + tig * 2;
            float2 v0, v1;
            v0.x = acc[mi][ni][0] * scale; v0.y = acc[mi][ni][1] * scale;
            v1.x = acc[mi][ni][2] * scale; v1.y = acc[mi][ni][3] * scale;
            *(float2*)(Cz + (size_t)row0 * ldc + col0) = v0;
            *(float2*)(Cz + (size_t)(row0 + 8) * ldc + col0) = v1;
        }
    }
}

// ---------------------------------------------------------------------------
// In-place row softmax + interleaved {hi,lo} plane output.
// ---------------------------------------------------------------------------
__global__ __launch_bounds__(256) void softmax_k(float* __restrict__ P,
    float2* __restrict__ p2)
{
    const size_t base = (size_t)blockIdx.x * SEQ;
    float* p = P + base;
    const int tid = threadIdx.x, lane = tid & 31, wid = tid >> 5;
    float4 a = ((const float4*)p)[tid * 2 + 0];
    float4 b = ((const float4*)p)[tid * 2 + 1];
    float x[8] = {a.x, a.y, a.z, a.w, b.x, b.y, b.z, b.w};
    __shared__ float red[8];

    float m = -INFINITY;
#pragma unroll
    for (int i = 0; i < 8; i++) m = fmaxf(m, x[i]);
#pragma unroll
    for (int o = 16; o > 0; o >>= 1) m = fmaxf(m, __shfl_xor_sync(0xffffffffu, m, o));
    if (lane == 0) red[wid] = m;
    __syncthreads();
    float mr = -INFINITY;
#pragma unroll
    for (int i = 0; i < 8; i++) mr = fmaxf(mr, red[i]);
    __syncthreads();

    float s = 0.0f;
#pragma unroll
    for (int i = 0; i < 8; i++) { x[i] = expf(x[i] - mr); s += x[i]; }
#pragma unroll
    for (int o = 16; o > 0; o >>= 1) s += __shfl_xor_sync(0xffffffffu, s, o);
    if (lane == 0) red[wid] = s;
    __syncthreads();
    float tot = 0.0f;
#pragma unroll
    for (int i = 0; i < 8; i++) tot += red[i];
    const float inv = 1.0f / tot;

    float4 o0, o1;
    o0.x = x[0] * inv; o0.y = x[1] * inv; o0.z = x[2] * inv; o0.w = x[3] * inv;
    o1.x = x[4] * inv; o1.y = x[5] * inv; o1.z = x[6] * inv; o1.w = x[7] * inv;
    ((float4*)p)[tid * 2 + 0] = o0;
    ((float4*)p)[tid * 2 + 1] = o1;

    float y[8] = {o0.x, o0.y, o0.z, o0.w, o1.x, o1.y, o1.z, o1.w};
#pragma unroll
    for (int i = 0; i < 8; i++) {
        float2 e;
        cvt2f(y[i], e.x, e.y);
        p2[base + tid * 8 + i] = e;
    }
}

// ---------------------------------------------------------------------------
extern "C" void kernel_launch(void* const* d_in, const int* in_sizes, int n_in,
                              void* d_out, int out_size)
{
    const float* query = (const float*)d_in[0];
    const float* key   = (const float*)d_in[1];
    const float* value = (const float*)d_in[2];
    const float* Wq = (const float*)d_in[3]; const float* bq = (const float*)d_in[4];
    const float* Wk = (const float*)d_in[5]; const float* bk = (const float*)d_in[6];
    const float* Wv = (const float*)d_in[7]; const float* bv = (const float*)d_in[8];

    float* out_attn = (float*)d_out;
    float* out_smax = (float*)d_out + (size_t)MSZ * DIM;

    float2 *q2, *k2, *vt2, *p2;
    cudaGetSymbolAddress((void**)&q2,  g_q2);
    cudaGetSymbolAddress((void**)&k2,  g_k2);
    cudaGetSymbolAddress((void**)&vt2, g_vt2);
    cudaGetSymbolAddress((void**)&p2,  g_p2);

    cudaFuncSetAttribute(gemm_proj, cudaFuncAttributeMaxDynamicSharedMemorySize, SMEM_PROJ);
    cudaFuncSetAttribute(gemm_big2, cudaFuncAttributeMaxDynamicSharedMemorySize, SMEM_BIG);

    // 1) q/k projections -> planes
    {
        dim3 grid(DIM / 128, MSZ / 128, 1);
        gemm_proj<<<grid, 256, SMEM_PROJ>>>(query, Wq, bq, 0, q2, DIM, 0, 0, 0, DIM);
        gemm_proj<<<grid, 256, SMEM_PROJ>>>(key,   Wk, bk, 0, k2, DIM, 0, 0, 0, DIM);
    }
    // 2) vT[b,e,s] = Wv[e,:] . value[b,s,:] + bv[e] -> planes
    {
        dim3 grid(SEQ / 128, DIM / 128, BATCH);
        gemm_proj<<<grid, 256, SMEM_PROJ>>>(Wv, value, bv, 1, vt2, DIM,
                                            0, (size_t)SEQ * DIM, (size_t)DIM * SEQ, SEQ);
    }
    // 3) scores = 10 * q @ k^T -> fp32 (3 products)
    {
        dim3 grid(SEQ / 128, SEQ / 128, BATCH);
        gemm_big2<<<grid, 256, SMEM_BIG>>>(q2, k2, out_smax, DIM, 10.0f,
                                           (size_t)SEQ * DIM, (size_t)SEQ * DIM,
                                           (size_t)SEQ * SEQ, SEQ, 3);
    }
    // 4) softmax in place + P planes
    softmax_k<<<MSZ, 256>>>(out_smax, p2);
    // 5) out = P @ vT^T (2 products: hh + lh)
    {
        dim3 grid(DIM / 128, SEQ / 128, BATCH);
        gemm_big2<<<grid, 256, SMEM_BIG>>>(p2, vt2, out_attn, SEQ, 1.0f,
                                           (size_t)SEQ * SEQ, (size_t)DIM * SEQ,
                                           (size_t)SEQ * DIM, DIM, 2);
    }
}

// round 9
// speedup vs baseline: 1.1491x; 1.1491x over previous
#include <cuda_runtime.h>
#include <math.h>

#define BATCH 8
#define SEQ   2048
#define DIM   1024
#define MSZ   (BATCH*SEQ)
typedef unsigned int u32;

// fp32 scratch (allocation-free rule)
__device__ float g_q [(size_t)MSZ*DIM];
__device__ float g_k [(size_t)MSZ*DIM];
__device__ float g_vt[(size_t)BATCH*DIM*SEQ];   // v transposed: [b][e][s]

// ---------------- helpers ----------------
__device__ __forceinline__ void cvt2f(float x, float& h, float& l) {
    u32 uh, ul;
    asm("cvt.rna.tf32.f32 %0, %1;" : "=r"(uh) : "f"(x));
    float r = x - __uint_as_float(uh);
    asm("cvt.rna.tf32.f32 %0, %1;" : "=r"(ul) : "f"(r));
    h = __uint_as_float(uh); l = __uint_as_float(ul);
}
__device__ __forceinline__ void mma8(float* c, const float* a, const float* b) {
    asm volatile(
        "mma.sync.aligned.m16n8k8.row.col.f32.tf32.tf32.f32 "
        "{%0,%1,%2,%3}, {%4,%5,%6,%7}, {%8,%9}, {%0,%1,%2,%3};"
        : "+f"(c[0]), "+f"(c[1]), "+f"(c[2]), "+f"(c[3])
        : "r"(__float_as_uint(a[0])), "r"(__float_as_uint(a[1])),
          "r"(__float_as_uint(a[2])), "r"(__float_as_uint(a[3])),
          "r"(__float_as_uint(b[0])), "r"(__float_as_uint(b[1])));
}

// ---------------------------------------------------------------------------
// C[m,n] = scale * sum_k A[m,k]*B[n,k] (+ bias)   NT gemm, split-TF32.
// Raw fp32 operands; per-chunk conversion into separate Ah/Al/Bh/Bl smem
// tiles; MMA phase is pure LDS.32 + HMMA. Tiles 128x128x32, 256 threads
// (8 warps 2m x 4n), warp tile 64x32, double-buffered (1 CTA/SM).
// nprod: 3 = hh+hl+lh (QK, projections), 2 = hh+lh (PV).
// ---------------------------------------------------------------------------
#define LDT 36                       // smem row stride (floats)
#define TILE_F (128*LDT)             // 4608 floats per plane tile
#define SMEM_BYTES (2*4*TILE_F*4)    // 2 bufs x {Ah,Al,Bh,Bl} = 147456 B

__global__ __launch_bounds__(256, 1) void gemm_s(
    const float* __restrict__ A, const float* __restrict__ B,
    const float* __restrict__ bias, int biasRow,
    float* __restrict__ C, int K, float scale,
    size_t sA, size_t sB, size_t sC, int ldc, int nprod)
{
    extern __shared__ float sm[];
    const int tid = threadIdx.x;
    const int wid = tid >> 5, lane = tid & 31;
    const int g = lane >> 2, tig = lane & 3;
    const int wm = (wid >> 2) * 64, wn = (wid & 3) * 32;
    const int z = blockIdx.z;

    const float* Ab = A + z * sA + (size_t)(blockIdx.y * 128) * K;
    const float* Bb = B + z * sB + (size_t)(blockIdx.x * 128) * K;

    const int lr  = tid >> 3;        // 0..31 (+32/64/96)
    const int lc4 = (tid & 7) * 4;   // 0..28

    float acc[4][4][4];
#pragma unroll
    for (int mi = 0; mi < 4; mi++)
#pragma unroll
        for (int ni = 0; ni < 4; ni++)
#pragma unroll
            for (int r = 0; r < 4; r++) acc[mi][ni][r] = 0.0f;

    const int nch = K / 32;
    float4 ra[4], rb[4];

    // LDG chunk c into registers
    auto load_regs = [&](int c) {
        const int k0 = c * 32;
#pragma unroll
        for (int i = 0; i < 4; i++) {
            const int row = lr + i * 32;
            ra[i] = *(const float4*)(Ab + (size_t)row * K + k0 + lc4);
            rb[i] = *(const float4*)(Bb + (size_t)row * K + k0 + lc4);
        }
    };
    // split regs -> {Ah,Al,Bh,Bl} tiles of buffer `buf`
    auto convert_store = [&](int buf) {
        float* Ah = sm + (buf * 4 + 0) * TILE_F;
        float* Al = sm + (buf * 4 + 1) * TILE_F;
        float* Bh = sm + (buf * 4 + 2) * TILE_F;
        float* Bl = sm + (buf * 4 + 3) * TILE_F;
#pragma unroll
        for (int i = 0; i < 4; i++) {
            const int off = (lr + i * 32) * LDT + lc4;
            float4 h, l;
            cvt2f(ra[i].x, h.x, l.x); cvt2f(ra[i].y, h.y, l.y);
            cvt2f(ra[i].z, h.z, l.z); cvt2f(ra[i].w, h.w, l.w);
            *(float4*)(Ah + off) = h; *(float4*)(Al + off) = l;
            cvt2f(rb[i].x, h.x, l.x); cvt2f(rb[i].y, h.y, l.y);
            cvt2f(rb[i].z, h.z, l.z); cvt2f(rb[i].w, h.w, l.w);
            *(float4*)(Bh + off) = h; *(float4*)(Bl + off) = l;
        }
    };

    load_regs(0);
    convert_store(0);
    __syncthreads();
    if (nch > 1) load_regs(1);

    for (int c = 0; c < nch; c++) {
        const int p = c & 1;
        if (c + 1 < nch) convert_store(p ^ 1);   // regs hold chunk c+1
        if (c + 2 < nch) load_regs(c + 2);

        const float* Ash = sm + (p * 4 + 0) * TILE_F;
        const float* Asl = sm + (p * 4 + 1) * TILE_F;
        const float* Bsh = sm + (p * 4 + 2) * TILE_F;
        const float* Bsl = sm + (p * 4 + 3) * TILE_F;

#pragma unroll
        for (int ks = 0; ks < 4; ks++) {
            const int kc = ks * 8 + tig;
            float ah[4][4], al[4][4], bh[4][2], bl[4][2];
#pragma unroll
            for (int mi = 0; mi < 4; mi++) {
                const int r0 = (wm + mi * 16 + g) * LDT;
                ah[mi][0] = Ash[r0 + kc];
                ah[mi][1] = Ash[r0 + 8 * LDT + kc];
                ah[mi][2] = Ash[r0 + kc + 4];
                ah[mi][3] = Ash[r0 + 8 * LDT + kc + 4];
                al[mi][0] = Asl[r0 + kc];
                al[mi][1] = Asl[r0 + 8 * LDT + kc];
                al[mi][2] = Asl[r0 + kc + 4];
                al[mi][3] = Asl[r0 + 8 * LDT + kc + 4];
            }
#pragma unroll
            for (int ni = 0; ni < 4; ni++) {
                const int rn = (wn + ni * 8 + g) * LDT;
                bh[ni][0] = Bsh[rn + kc];
                bh[ni][1] = Bsh[rn + kc + 4];
                bl[ni][0] = Bsl[rn + kc];
                bl[ni][1] = Bsl[rn + kc + 4];
            }
            // hh
#pragma unroll
            for (int mi = 0; mi < 4; mi++)
#pragma unroll
                for (int ni = 0; ni < 4; ni++) mma8(acc[mi][ni], ah[mi], bh[ni]);
            // lh
#pragma unroll
            for (int mi = 0; mi < 4; mi++)
#pragma unroll
                for (int ni = 0; ni < 4; ni++) mma8(acc[mi][ni], al[mi], bh[ni]);
            // hl (skipped for PV)
            if (nprod == 3) {
#pragma unroll
                for (int mi = 0; mi < 4; mi++)
#pragma unroll
                    for (int ni = 0; ni < 4; ni++) mma8(acc[mi][ni], ah[mi], bl[ni]);
            }
        }
        __syncthreads();
    }

    // ---------------- epilogue ----------------
    float* Cz = C + z * sC;
#pragma unroll
    for (int mi = 0; mi < 4; mi++) {
        const int row0 = blockIdx.y * 128 + wm + mi * 16 + g;
        const float br0 = (bias && biasRow) ? bias[row0] : 0.0f;
        const float br1 = (bias && biasRow) ? bias[row0 + 8] : 0.0f;
#pragma unroll
        for (int ni = 0; ni < 4; ni++) {
            const int col0 = blockIdx.x * 128 + wn + ni * 8 + tig * 2;
            float2 v0, v1;
            v0.x = acc[mi][ni][0] * scale; v0.y = acc[mi][ni][1] * scale;
            v1.x = acc[mi][ni][2] * scale; v1.y = acc[mi][ni][3] * scale;
            if (bias) {
                if (biasRow) { v0.x += br0; v0.y += br0; v1.x += br1; v1.y += br1; }
                else {
                    const float b0 = bias[col0], b1 = bias[col0 + 1];
                    v0.x += b0; v0.y += b1; v1.x += b0; v1.y += b1;
                }
            }
            *(float2*)(Cz + (size_t)row0 * ldc + col0) = v0;
            *(float2*)(Cz + (size_t)(row0 + 8) * ldc + col0) = v1;
        }
    }
}

// ---------------------------------------------------------------------------
// In-place row softmax over SEQ columns. One block (256 thr) per row.
// ---------------------------------------------------------------------------
__global__ __launch_bounds__(256) void softmax_kernel(float* __restrict__ P)
{
    float* p = P + (size_t)blockIdx.x * SEQ;
    const int tid = threadIdx.x, lane = tid & 31, wid = tid >> 5;
    float4 a = ((const float4*)p)[tid * 2 + 0];
    float4 b = ((const float4*)p)[tid * 2 + 1];
    float x[8] = {a.x, a.y, a.z, a.w, b.x, b.y, b.z, b.w};
    __shared__ float red[8];

    float m = -INFINITY;
#pragma unroll
    for (int i = 0; i < 8; i++) m = fmaxf(m, x[i]);
#pragma unroll
    for (int o = 16; o > 0; o >>= 1) m = fmaxf(m, __shfl_xor_sync(0xffffffffu, m, o));
    if (lane == 0) red[wid] = m;
    __syncthreads();
    float mr = -INFINITY;
#pragma unroll
    for (int i = 0; i < 8; i++) mr = fmaxf(mr, red[i]);
    __syncthreads();

    float s = 0.0f;
#pragma unroll
    for (int i = 0; i < 8; i++) { x[i] = expf(x[i] - mr); s += x[i]; }
#pragma unroll
    for (int o = 16; o > 0; o >>= 1) s += __shfl_xor_sync(0xffffffffu, s, o);
    if (lane == 0) red[wid] = s;
    __syncthreads();
    float tot = 0.0f;
#pragma unroll
    for (int i = 0; i < 8; i++) tot += red[i];
    const float inv = 1.0f / tot;

    float4 o0, o1;
    o0.x = x[0] * inv; o0.y = x[1] * inv; o0.z = x[2] * inv; o0.w = x[3] * inv;
    o1.x = x[4] * inv; o1.y = x[5] * inv; o1.z = x[6] * inv; o1.w = x[7] * inv;
    ((float4*)p)[tid * 2 + 0] = o0;
    ((float4*)p)[tid * 2 + 1] = o1;
}

// ---------------------------------------------------------------------------
extern "C" void kernel_launch(void* const* d_in, const int* in_sizes, int n_in,
                              void* d_out, int out_size)
{
    const float* query = (const float*)d_in[0];
    const float* key   = (const float*)d_in[1];
    const float* value = (const float*)d_in[2];
    const float* Wq = (const float*)d_in[3]; const float* bq = (const float*)d_in[4];
    const float* Wk = (const float*)d_in[5]; const float* bk = (const float*)d_in[6];
    const float* Wv = (const float*)d_in[7]; const float* bv = (const float*)d_in[8];

    float* out_attn = (float*)d_out;
    float* out_smax = (float*)d_out + (size_t)MSZ * DIM;

    float *q, *k, *vt;
    cudaGetSymbolAddress((void**)&q,  g_q);
    cudaGetSymbolAddress((void**)&k,  g_k);
    cudaGetSymbolAddress((void**)&vt, g_vt);

    cudaFuncSetAttribute(gemm_s, cudaFuncAttributeMaxDynamicSharedMemorySize, SMEM_BYTES);

    // 1) q = query @ Wq^T + bq ; k = key @ Wk^T + bk
    {
        dim3 grid(DIM / 128, MSZ / 128, 1);
        gemm_s<<<grid, 256, SMEM_BYTES>>>(query, Wq, bq, 0, q, DIM, 1.0f, 0, 0, 0, DIM, 3);
        gemm_s<<<grid, 256, SMEM_BYTES>>>(key,   Wk, bk, 0, k, DIM, 1.0f, 0, 0, 0, DIM, 3);
    }
    // 2) vT[b,e,s] = Wv[e,:] . value[b,s,:] + bv[e]
    {
        dim3 grid(SEQ / 128, DIM / 128, BATCH);
        gemm_s<<<grid, 256, SMEM_BYTES>>>(Wv, value, bv, 1, vt, DIM, 1.0f,
                                          0, (size_t)SEQ * DIM, (size_t)DIM * SEQ, SEQ, 3);
    }
    // 3) scores = 10 * q @ k^T
    {
        dim3 grid(SEQ / 128, SEQ / 128, BATCH);
        gemm_s<<<grid, 256, SMEM_BYTES>>>(q, k, nullptr, 0, out_smax, DIM, 10.0f,
                                          (size_t)SEQ * DIM, (size_t)SEQ * DIM,
                                          (size_t)SEQ * SEQ, SEQ, 3);
    }
    // 4) softmax in place
    softmax_kernel<<<MSZ, 256>>>(out_smax);
    // 5) out = P @ vT^T  (2 products: hh + lh)
    {
        dim3 grid(DIM / 128, SEQ / 128, BATCH);
        gemm_s<<<grid, 256, SMEM_BYTES>>>(out_smax, vt, nullptr, 0, out_attn, SEQ, 1.0f,
                                          (size_t)SEQ * SEQ, (size_t)DIM * SEQ,
                                          (size_t)SEQ * DIM, DIM, 2);
    }
}